// round 15
// baseline (speedup 1.0000x reference)
#include <cuda_runtime.h>
#include <cuda_fp16.h>

#define BB 32
#define TT_IN 1024
#define TP 1025
#define EMB 384
#define GC 96
#define NWARPS 12
#define NCHUNK 5
#define SUBS 7            // m32-subtiles per chunk (5*7*32 = 1120 >= 1025)
#define ROWS 32           // time rows per subtile
#define XR 34             // staged rows (ROWS + 2 halo)
#define XP (XR * 48)      // staged half2 pairs = 1632
#define ZWARPS 64         // tail-zero warps per batch
#define NPART 16          // 4 groups * 4 n-groups partials
#define PWARPS ((BB * TP + 31) / 32)

#define SW_SCAT (BB * TP)
#define SW_TOT  (SW_SCAT + BB * ZWARPS)

// Dynamic smem: two A buffers of XP u32 (f16x2 pairs), then P exchange.
#define XS_U32   XP
#define SMEM_BYTES (2 * XS_U32 * 4 + 2 * NWARPS * 32 * 3 * 16)   // 13056+36864

// Scratch (device globals: no allocations allowed)
__device__ int          g_cum[BB * TP];
__device__ unsigned int g_wB[4 * NWARPS * 18 * 2 * 32];   // f16x2 B fragments
__device__ float        g_part[NPART * BB * TP];          // pred partials

#define MMA_F16(d0,d1,d2,d3, a0,a1,a2,a3, b0,b1)                           \
    asm("mma.sync.aligned.m16n8k16.row.col.f32.f16.f16.f32 "               \
        "{%0,%1,%2,%3}, {%4,%5,%6,%7}, {%8,%9}, {%0,%1,%2,%3};"            \
        : "+f"(d0), "+f"(d1), "+f"(d2), "+f"(d3)                           \
        : "r"(a0), "r"(a1), "r"(a2), "r"(a3), "r"(b0), "r"(b1))

__device__ __forceinline__ unsigned pack_h2(float v0, float v1) {
    __half2 h = __floats2half2_rn(v0, v1);
    return *reinterpret_cast<unsigned*>(&h);
}

// A staging word index: channel pair pp (0..47) within the 96-ch group, row.
// 32-ch (2 K-chunk) groups of 16 pairs; within a group, thread t4's four
// fragment pairs {a0_e0, a2_e0, a0_e1, a2_e1} land in words 4*t4..4*t4+3.
__device__ __forceinline__ int stage_idx(int row, int pp) {
    int ks2 = pp >> 4;          // 2-chunk group (0..2)
    int q16 = pp & 15;          // pair within group
    int e   = q16 >> 3;         // chunk parity
    int p   = q16 & 7;          // pair within chunk
    return row * 48 + ks2 * 16 + ((p & 3) << 2) + (p >> 2) + 2 * e;
}

// ---------------------------------------------------------------------------
// Merged prep: blocks [0,32) = per-batch cumsum; blocks >= 32 = pack conv1
// weights into f16 m16n8k16 B-fragment order:
// b_r(kst, lane) = {W[i][n], W[i+1][n]}, i = (kst%6)*16 + 2*(lane&3) + 8r,
// tap = kst/6, n = nt*8 + lane/4.
// ---------------------------------------------------------------------------
__global__ void prep_kernel(const int* __restrict__ dur,
                            const float* __restrict__ w1) {
    if (blockIdx.x < BB) {
        const int b = blockIdx.x;
        const int tid = threadIdx.x;           // 256 threads
        const int CH = 5;
        __shared__ int part[256];

        int base = tid * CH;
        int s = 0;
#pragma unroll
        for (int j = 0; j < CH; j++) {
            int p = base + j;
            if (p < TP) s += dur[b * TP + p];
        }
        part[tid] = s;
        __syncthreads();

        for (int off = 1; off < 256; off <<= 1) {
            int v = (tid >= off) ? part[tid - off] : 0;
            __syncthreads();
            part[tid] += v;
            __syncthreads();
        }

        int run = (tid > 0) ? part[tid - 1] : 0;
#pragma unroll
        for (int j = 0; j < CH; j++) {
            int p = base + j;
            if (p < TP) {
                run += dur[b * TP + p];
                g_cum[b * TP + p] = run;
            }
        }
    } else {
        int t = (blockIdx.x - BB) * blockDim.x + threadIdx.x;
        if (t >= 4 * NWARPS * 18 * 32) return;
        int lane = t & 31;
        int rest = t >> 5;
        int kst = rest % 18;
        int nt  = (rest / 18) % NWARPS;
        int g   = rest / (18 * NWARPS);

        int kk = kst / 6;                  // conv tap
        int n  = nt * 8 + (lane >> 2);
        int C  = g * GC + n;
#pragma unroll
        for (int r = 0; r < 2; r++) {
            int i = (kst % 6) * 16 + 2 * (lane & 3) + 8 * r;
            float w0 = w1[C * (GC * 3) + i * 3 + kk];
            float w1v = w1[C * (GC * 3) + (i + 1) * 3 + kk];
            g_wB[(((g * NWARPS + nt) * 18 + kst) * 2 + r) * 32 + lane] =
                pack_h2(w0, w1v);
        }
    }
}

// ---------------------------------------------------------------------------
// fp16 tensor-core duration predictor, m32 subtiles, k-split (R14 structure).
// grid = (BB, 4 groups, NCHUNK); block = 384 = 12 warps.
// Warp (ng = wid&3, kt = wid>>2): n-tiles {3ng..3ng+2}, conv tap kt.
// ---------------------------------------------------------------------------
extern __shared__ unsigned int dsm[];

__global__ __launch_bounds__(384)
void conv_mma_kernel(const float* __restrict__ ph,
                     const float* __restrict__ sil,
                     const float* __restrict__ b1,
                     const float* __restrict__ w2) {
    unsigned int* xs[2] = { dsm, dsm + XS_U32 };
    float4* P = (float4*)(dsm + 2 * XS_U32);

    const int b     = blockIdx.x;
    const int g     = blockIdx.y;
    const int chunk = blockIdx.z;
    const int tbase = chunk * (SUBS * ROWS);
    const int tid   = threadIdx.x;
    const int wid   = tid >> 5;
    const int lane  = tid & 31;
    const int g4    = lane >> 2;
    const int t4    = lane & 3;
    const int ng    = wid & 3;
    const int kt    = wid >> 2;

    const float2* ph2  = (const float2*)ph;
    const float2* sil2 = (const float2*)sil;

    // B fragments: 3 n-tiles x 6 K16-chunks x 2 regs = 36 regs.
    unsigned int Bf[6][2][3];
#pragma unroll
    for (int j = 0; j < 3; j++) {
        const int nt = ng * 3 + j;
        const unsigned int* wb =
            g_wB + (((g * NWARPS + nt) * 18 + kt * 6) * 2) * 32 + lane;
#pragma unroll
        for (int kc = 0; kc < 6; kc++) {
            Bf[kc][0][j] = wb[(kc * 2 + 0) * 32];
            Bf[kc][1][j] = wb[(kc * 2 + 1) * 32];
        }
    }

    // Epilogue constants (readback warps 0..3 only).
    float w2v[3][2], b1v[3][2];
    if (wid < 4) {
#pragma unroll
        for (int j = 0; j < 3; j++) {
#pragma unroll
            for (int h = 0; h < 2; h++) {
                int C = g * GC + (wid * 3 + j) * 8 + t4 * 2 + h;
                w2v[j][h] = w2[C];
                b1v[j][h] = b1[C];
            }
        }
    }

    // Prologue: stage subtile 0 (f16x2 pairs, permuted layout).
    {
        const int ts0 = tbase;
#pragma unroll
        for (int i = 0; i < 5; i++) {
            int e = tid + i * 384;
            if (e < XP) {
                int row = e / 48, pp = e - row * 48;
                int tg = ts0 - 1 + row;
                float2 v = make_float2(0.f, 0.f);
                if ((unsigned)tg < TT_IN) v = ph2[((size_t)b * TT_IN + tg) * 192 + g * 48 + pp];
                else if (tg == TT_IN)     v = sil2[g * 48 + pp];
                xs[0][stage_idx(row, pp)] = pack_h2(v.x, v.y);
            }
        }
    }
    __syncthreads();

    for (int sub = 0; sub < SUBS; sub++) {
        const int tsub0 = tbase + sub * ROWS;
        if (tsub0 >= TP) break;              // block-uniform
        const int cur = sub & 1;
        const bool have_next = (sub + 1 < SUBS) && (tbase + (sub + 1) * ROWS < TP);

        // Prefetch next subtile (warps 4..11, 256 thr), converted at load.
        unsigned xv[7];
        if (have_next && wid >= 4) {
            const int ts1 = tsub0 + ROWS;
#pragma unroll
            for (int i = 0; i < 7; i++) {
                int e = (tid - 128) + i * 256;
                float2 v = make_float2(0.f, 0.f);
                if (e < XP) {
                    int row = e / 48, pp = e - row * 48;
                    int tg = ts1 - 1 + row;
                    if ((unsigned)tg < TT_IN) v = ph2[((size_t)b * TT_IN + tg) * 192 + g * 48 + pp];
                    else if (tg == TT_IN)     v = sil2[g * 48 + pp];
                }
                xv[i] = pack_h2(v.x, v.y);
            }
        }

        // MMA: two m16 tiles (q=0,1); per tile 3 LDS.128 pairs, 18 HMMA.
        float acc[2][3][4];
#pragma unroll
        for (int q = 0; q < 2; q++)
#pragma unroll
            for (int j = 0; j < 3; j++)
#pragma unroll
                for (int r = 0; r < 4; r++) acc[q][j][r] = 0.f;

        {
            const uint4* U = (const uint4*)xs[cur];
#pragma unroll
            for (int q = 0; q < 2; q++) {
                const int r0 = q * 16 + g4 + kt;
#pragma unroll
                for (int ks2 = 0; ks2 < 3; ks2++) {
                    uint4 A0 = U[r0 * 12 + ks2 * 4 + t4];
                    uint4 A1 = U[(r0 + 8) * 12 + ks2 * 4 + t4];
                    // chunk e=0: pairs {A0.x=a0, A1.x=a1, A0.y=a2, A1.y=a3}
#pragma unroll
                    for (int j = 0; j < 3; j++)
                        MMA_F16(acc[q][j][0], acc[q][j][1], acc[q][j][2], acc[q][j][3],
                                A0.x, A1.x, A0.y, A1.y,
                                Bf[2 * ks2][0][j], Bf[2 * ks2][1][j]);
                    // chunk e=1
#pragma unroll
                    for (int j = 0; j < 3; j++)
                        MMA_F16(acc[q][j][0], acc[q][j][1], acc[q][j][2], acc[q][j][3],
                                A0.z, A1.z, A0.w, A1.w,
                                Bf[2 * ks2 + 1][0][j], Bf[2 * ks2 + 1][1][j]);
                }
            }
        }

        // Publish pre-ReLU k-partials for both tiles.
#pragma unroll
        for (int q = 0; q < 2; q++)
#pragma unroll
            for (int j = 0; j < 3; j++)
                P[((q * NWARPS + wid) * 32 + lane) * 3 + j] =
                    make_float4(acc[q][j][0], acc[q][j][1], acc[q][j][2], acc[q][j][3]);
        __syncthreads();

        if (wid < 4) {
#pragma unroll
            for (int q = 0; q < 2; q++) {
                float vlo = 0.f, vhi = 0.f;
#pragma unroll
                for (int j = 0; j < 3; j++) {
                    float4 p0 = P[((q * NWARPS + wid)     * 32 + lane) * 3 + j];
                    float4 p1 = P[((q * NWARPS + 4 + wid) * 32 + lane) * 3 + j];
                    float4 p2 = P[((q * NWARPS + 8 + wid) * 32 + lane) * 3 + j];
                    float sx = p0.x + p1.x + p2.x;
                    float sy = p0.y + p1.y + p2.y;
                    float sz = p0.z + p1.z + p2.z;
                    float sw = p0.w + p1.w + p2.w;
                    vlo += w2v[j][0] * fmaxf(sx + b1v[j][0], 0.f)
                         + w2v[j][1] * fmaxf(sy + b1v[j][1], 0.f);
                    vhi += w2v[j][0] * fmaxf(sz + b1v[j][0], 0.f)
                         + w2v[j][1] * fmaxf(sw + b1v[j][1], 0.f);
                }
                vlo += __shfl_xor_sync(0xffffffffu, vlo, 1);
                vlo += __shfl_xor_sync(0xffffffffu, vlo, 2);
                vhi += __shfl_xor_sync(0xffffffffu, vhi, 1);
                vhi += __shfl_xor_sync(0xffffffffu, vhi, 2);
                if (t4 == 0) {
                    const size_t base = ((size_t)(g * 4 + wid) * BB + b) * TP;
                    int t = tsub0 + q * 16 + g4;
                    if (t < TP)     g_part[base + t] = vlo;
                    if (t + 8 < TP) g_part[base + t + 8] = vhi;
                }
            }
        } else if (have_next) {
            const int nxt = cur ^ 1;
#pragma unroll
            for (int i = 0; i < 7; i++) {
                int e = (tid - 128) + i * 256;
                if (e < XP) {
                    int row = e / 48, pp = e - row * 48;
                    xs[nxt][stage_idx(row, pp)] = xv[i];
                }
            }
        }
        __syncthreads();
    }
}

// ---------------------------------------------------------------------------
// SCATTER + tail-zero + pred-sum, one kernel (validated bodies).
// ---------------------------------------------------------------------------
__global__ void scatter_kernel(const float* __restrict__ ph,
                               const float* __restrict__ sil,
                               const float* __restrict__ b2,
                               float* __restrict__ out,
                               float* __restrict__ dpred,
                               int t_out) {
    const int w = (blockIdx.x * blockDim.x + threadIdx.x) >> 5;
    const int lane = threadIdx.x & 31;

    if (w < SW_SCAT) {
        const int b = w / TP;
        const int j = w - b * TP;

        const int hi = g_cum[b * TP + j];
        const int lo = j ? g_cum[b * TP + j - 1] : 0;
        const int d = hi - lo;
        if (d <= 0) return;

        const float4* src = (j < TT_IN)
            ? (const float4*)(ph + ((size_t)b * TT_IN + j) * EMB)
            : (const float4*)sil;
        float4 r0 = __ldcs(src + lane);
        float4 r1 = __ldcs(src + 32 + lane);
        float4 r2 = __ldcs(src + 64 + lane);

        float4* dst = (float4*)(out + ((size_t)b * t_out + lo) * EMB);
        for (int f = 0; f < d; f++, dst += EMB / 4) {
            __stcs(dst + lane,      r0);
            __stcs(dst + 32 + lane, r1);
            __stcs(dst + 64 + lane, r2);
        }
    } else if (w < SW_TOT) {
        const int zw = w - SW_SCAT;
        const int b  = zw / ZWARPS;
        const int zi = zw - b * ZWARPS;
        const int tot = g_cum[b * TP + TP - 1];
        const float4 z = make_float4(0.f, 0.f, 0.f, 0.f);
        for (int t = tot + zi; t < t_out; t += ZWARPS) {
            float4* dst = (float4*)(out + ((size_t)b * t_out + t) * EMB);
            __stcs(dst + lane,      z);
            __stcs(dst + 32 + lane, z);
            __stcs(dst + 64 + lane, z);
        }
    } else {
        const int pw = w - SW_TOT;
        if (pw >= PWARPS) return;
        const int i = pw * 32 + lane;
        if (i >= BB * TP) return;
        float s = b2[0];
#pragma unroll
        for (int q = 0; q < NPART; q++) s += g_part[(size_t)q * BB * TP + i];
        dpred[i] = s;
    }
}

// ---------------------------------------------------------------------------
// Launch
// ---------------------------------------------------------------------------
extern "C" void kernel_launch(void* const* d_in, const int* in_sizes, int n_in,
                              void* d_out, int out_size) {
    const float* ph  = (const float*)d_in[0];   // [32,1024,384]
    const float* sil = (const float*)d_in[1];   // [384]
    const float* w1  = (const float*)d_in[2];   // [384,96,3]
    const float* b1  = (const float*)d_in[3];   // [384]
    const float* w2  = (const float*)d_in[4];   // [1,384,1]
    const float* b2  = (const float*)d_in[5];   // [1]
    const int*   dur = (const int*)d_in[6];     // [32,1025]

    const int t_out = (out_size - BB * TP) / (BB * EMB);

    float* out_exp  = (float*)d_out;                             // [B,t_out,EMB]
    float* out_pred = (float*)d_out + (size_t)BB * t_out * EMB;  // [B,TP]

    const int wblocks = (4 * NWARPS * 18 * 32 + 255) / 256;
    prep_kernel<<<BB + wblocks, 256>>>(dur, w1);

    cudaFuncSetAttribute(conv_mma_kernel,
                         cudaFuncAttributeMaxDynamicSharedMemorySize, SMEM_BYTES);
    dim3 cgrid(BB, 4, NCHUNK);
    conv_mma_kernel<<<cgrid, 384, SMEM_BYTES>>>(ph, sil, b1, w2);

    const int warps = SW_TOT + PWARPS;
    scatter_kernel<<<(warps * 32 + 255) / 256, 256>>>(ph, sil, b2,
                                                      out_exp, out_pred, t_out);
}

// round 17
// speedup vs baseline: 1.2231x; 1.2231x over previous
#include <cuda_runtime.h>

#define BB 32
#define TT_IN 1024
#define TP 1025
#define EMB 384
#define GC 96
#define NWARPS 12
#define NKS 36            // total K-steps: 3 taps * 96 ch / 8
#define ROWS 32           // time rows per subtile
#define XR 34             // staged rows (ROWS + 2 halo)
#define XE (XR * GC)      // staged elements = 3264
#define ZWARPS 64         // tail-zero warps per batch
#define NPART 16          // 4 groups * 4 n-groups partials
#define PWARPS ((BB * TP + 31) / 32)

#define SUBS_PER_PAIR 33                  // 33*32 = 1056 >= 1025
#define TOTAL_SUBS (128 * SUBS_PER_PAIR)  // 4224
#define CBLOCKS 592                       // 148 SMs * 4 — exact waves

#define SW_SCAT (BB * TP)
#define SW_TOT  (SW_SCAT + BB * ZWARPS)

#define XS_U32   (XR * 50 * 2)                     // 3400 u32 per buffer
#define SMEM_BYTES (2 * XS_U32 * 4 + 2 * NWARPS * 32 * 3 * 16)   // 64064

// Scratch (device globals: no allocations allowed)
__device__ int          g_cum[BB * TP];
__device__ unsigned int g_wB[4 * NWARPS * NKS * 2 * 32];  // tf32 B fragments
__device__ float        g_part[NPART * BB * TP];          // pred partials

#define CVT_TF32(u, f) asm("cvt.rna.tf32.f32 %0, %1;" : "=r"(u) : "f"(f))

#define MMA_TF32(d0,d1,d2,d3, a0,a1,a2,a3, b0,b1)                          \
    asm("mma.sync.aligned.m16n8k8.row.col.f32.tf32.tf32.f32 "              \
        "{%0,%1,%2,%3}, {%4,%5,%6,%7}, {%8,%9}, {%0,%1,%2,%3};"            \
        : "+f"(d0), "+f"(d1), "+f"(d2), "+f"(d3)                           \
        : "r"(a0), "r"(a1), "r"(a2), "r"(a3), "r"(b0), "r"(b1))

// Permuted pair staging address (validated R9/R14).
__device__ __forceinline__ int stage_idx(int row, int col) {
    int ki = col >> 3, rem = col & 7;
    return (row * 50 + (rem & 3) * 12 + ki) * 2 + (rem >> 2);
}

// ---------------------------------------------------------------------------
// Merged prep: blocks [0,32) = per-batch cumsum; blocks >= 32 = pack conv1
// weights into tf32 mma B-fragment order (validated R4/R8/R9/R14).
// ---------------------------------------------------------------------------
__global__ void prep_kernel(const int* __restrict__ dur,
                            const float* __restrict__ w1) {
    if (blockIdx.x < BB) {
        const int b = blockIdx.x;
        const int tid = threadIdx.x;
        const int CH = 5;
        __shared__ int part[256];

        int base = tid * CH;
        int s = 0;
#pragma unroll
        for (int j = 0; j < CH; j++) {
            int p = base + j;
            if (p < TP) s += dur[b * TP + p];
        }
        part[tid] = s;
        __syncthreads();

        for (int off = 1; off < 256; off <<= 1) {
            int v = (tid >= off) ? part[tid - off] : 0;
            __syncthreads();
            part[tid] += v;
            __syncthreads();
        }

        int run = (tid > 0) ? part[tid - 1] : 0;
#pragma unroll
        for (int j = 0; j < CH; j++) {
            int p = base + j;
            if (p < TP) {
                run += dur[b * TP + p];
                g_cum[b * TP + p] = run;
            }
        }
    } else {
        int t = (blockIdx.x - BB) * blockDim.x + threadIdx.x;
        if (t >= 4 * NWARPS * NKS * 32) return;
        int lane = t & 31;
        int rest = t >> 5;
        int ks = rest % NKS;
        int nt = (rest / NKS) % NWARPS;
        int g  = rest / (NKS * NWARPS);

        int kk = ks / 12;
        int n  = nt * 8 + (lane >> 2);
        int C  = g * GC + n;
#pragma unroll
        for (int r = 0; r < 2; r++) {
            int i = (ks % 12) * 8 + (lane & 3) + 4 * r;
            float w = w1[C * (GC * 3) + i * 3 + kk];
            unsigned u; CVT_TF32(u, w);
            g_wB[(((g * NWARPS + nt) * NKS + ks) * 2 + r) * 32 + lane] = u;
        }
    }
}

// ---------------------------------------------------------------------------
// tf32 tensor-core duration predictor, m32 subtiles, BALANCED LINEAR GRID.
// 592 blocks; block i owns subtiles [i*264/37, (i+1)*264/37) of the global
// 4224-subtile sequence S -> (pair=S/33, sub=S%33), pair=(g<<5)|b.
// B fragments / epilogue constants reload only when g changes (rare).
// Pipeline, fragment math, P-exchange, epilogue = R14 verbatim.
// ---------------------------------------------------------------------------
extern __shared__ unsigned int dsm[];

__global__ __launch_bounds__(384)
void conv_mma_kernel(const float* __restrict__ ph,
                     const float* __restrict__ sil,
                     const float* __restrict__ b1,
                     const float* __restrict__ w2) {
    unsigned int* xs[2] = { dsm, dsm + XS_U32 };
    float4* P = (float4*)(dsm + 2 * XS_U32);

    const int tid  = threadIdx.x;
    const int wid  = tid >> 5;
    const int lane = tid & 31;
    const int g4   = lane >> 2;
    const int t4   = lane & 3;
    const int ng   = wid & 3;
    const int kt   = wid >> 2;

    const int S0   = (blockIdx.x * 264) / 37;
    const int Send = ((blockIdx.x + 1) * 264) / 37;

    unsigned int Breg0[12][3], Breg1[12][3];
    float w2v[3][2], b1v[3][2];
    int g_cur = -1;

    // Prologue: stage subtile S0 into buffer 0.
    {
        const int p0 = S0 / SUBS_PER_PAIR;
        const int ts0 = (S0 - p0 * SUBS_PER_PAIR) * ROWS;
        const int bb = p0 & 31, gg = p0 >> 5;
#pragma unroll
        for (int i = 0; i < 9; i++) {
            int e = tid + i * 384;
            if (e < XE) {
                int row = e / GC, col = e - row * GC;
                int tg = ts0 - 1 + row;
                float v = 0.f;
                if ((unsigned)tg < TT_IN) v = ph[((size_t)bb * TT_IN + tg) * EMB + gg * GC + col];
                else if (tg == TT_IN)     v = sil[gg * GC + col];
                unsigned u; CVT_TF32(u, v);
                xs[0][stage_idx(row, col)] = u;
            }
        }
    }
    __syncthreads();

    for (int s = S0; s < Send; s++) {
        const int p   = s / SUBS_PER_PAIR;
        const int sub = s - p * SUBS_PER_PAIR;
        const int b   = p & 31;
        const int g   = p >> 5;
        const int tsub0 = sub * ROWS;
        const int cur = (s - S0) & 1;
        const bool have_next = (s + 1 < Send);

        // (Re)load B fragments + epilogue constants on g change (rare).
        if (g != g_cur) {
            g_cur = g;
#pragma unroll
            for (int j = 0; j < 3; j++) {
                const int nt = ng * 3 + j;
                const unsigned int* wb =
                    g_wB + ((g * NWARPS + nt) * NKS) * 2 * 32 + lane;
#pragma unroll
                for (int ksl = 0; ksl < 12; ksl++) {
                    const int ks = kt * 12 + ksl;
                    Breg0[ksl][j] = wb[(ks * 2 + 0) * 32];
                    Breg1[ksl][j] = wb[(ks * 2 + 1) * 32];
                }
            }
            if (wid < 4) {
#pragma unroll
                for (int j = 0; j < 3; j++) {
#pragma unroll
                    for (int h = 0; h < 2; h++) {
                        int C = g * GC + (wid * 3 + j) * 8 + t4 * 2 + h;
                        w2v[j][h] = w2[C];
                        b1v[j][h] = b1[C];
                    }
                }
            }
        }

        // Prefetch next subtile's x into registers (warps 4..11, 256 thr).
        float xv[13];
        if (have_next && wid >= 4) {
            const int p1   = (s + 1) / SUBS_PER_PAIR;
            const int ts1  = ((s + 1) - p1 * SUBS_PER_PAIR) * ROWS;
            const int bb1  = p1 & 31, gg1 = p1 >> 5;
#pragma unroll
            for (int i = 0; i < 13; i++) {
                int e = (tid - 128) + i * 256;
                float v = 0.f;
                if (e < XE) {
                    int row = e / GC, col = e - row * GC;
                    int tg = ts1 - 1 + row;
                    if ((unsigned)tg < TT_IN) v = ph[((size_t)bb1 * TT_IN + tg) * EMB + gg1 * GC + col];
                    else if (tg == TT_IN)     v = sil[gg1 * GC + col];
                }
                xv[i] = v;
            }
        }

        // MMA: two m16 tiles (q=0,1), rows (q*16+g4+kt, +8), 12 K-steps each.
        float acc[2][3][4];
#pragma unroll
        for (int q = 0; q < 2; q++)
#pragma unroll
            for (int j = 0; j < 3; j++)
#pragma unroll
                for (int r = 0; r < 4; r++) acc[q][j][r] = 0.f;

        {
            const uint4* U = (const uint4*)xs[cur];
#pragma unroll
            for (int q = 0; q < 2; q++) {
                const int i0 = (q * 16 + g4 + kt) * 25 + t4 * 6;
                const int i1 = i0 + 8 * 25;
#pragma unroll
                for (int pq = 0; pq < 6; pq++) {
                    uint4 A0 = U[i0 + pq];
                    uint4 A1 = U[i1 + pq];
#pragma unroll
                    for (int j = 0; j < 3; j++)
                        MMA_TF32(acc[q][j][0], acc[q][j][1], acc[q][j][2], acc[q][j][3],
                                 A0.x, A1.x, A0.y, A1.y,
                                 Breg0[2 * pq][j], Breg1[2 * pq][j]);
#pragma unroll
                    for (int j = 0; j < 3; j++)
                        MMA_TF32(acc[q][j][0], acc[q][j][1], acc[q][j][2], acc[q][j][3],
                                 A0.z, A1.z, A0.w, A1.w,
                                 Breg0[2 * pq + 1][j], Breg1[2 * pq + 1][j]);
                }
            }
        }

        // Publish pre-ReLU k-partials for both tiles.
#pragma unroll
        for (int q = 0; q < 2; q++)
#pragma unroll
            for (int j = 0; j < 3; j++)
                P[((q * NWARPS + wid) * 32 + lane) * 3 + j] =
                    make_float4(acc[q][j][0], acc[q][j][1], acc[q][j][2], acc[q][j][3]);
        __syncthreads();

        if (wid < 4) {
#pragma unroll
            for (int q = 0; q < 2; q++) {
                float vlo = 0.f, vhi = 0.f;
#pragma unroll
                for (int j = 0; j < 3; j++) {
                    float4 p0 = P[((q * NWARPS + wid)     * 32 + lane) * 3 + j];
                    float4 p1 = P[((q * NWARPS + 4 + wid) * 32 + lane) * 3 + j];
                    float4 p2 = P[((q * NWARPS + 8 + wid) * 32 + lane) * 3 + j];
                    float sx = p0.x + p1.x + p2.x;
                    float sy = p0.y + p1.y + p2.y;
                    float sz = p0.z + p1.z + p2.z;
                    float sw = p0.w + p1.w + p2.w;
                    vlo += w2v[j][0] * fmaxf(sx + b1v[j][0], 0.f)
                         + w2v[j][1] * fmaxf(sy + b1v[j][1], 0.f);
                    vhi += w2v[j][0] * fmaxf(sz + b1v[j][0], 0.f)
                         + w2v[j][1] * fmaxf(sw + b1v[j][1], 0.f);
                }
                vlo += __shfl_xor_sync(0xffffffffu, vlo, 1);
                vlo += __shfl_xor_sync(0xffffffffu, vlo, 2);
                vhi += __shfl_xor_sync(0xffffffffu, vhi, 1);
                vhi += __shfl_xor_sync(0xffffffffu, vhi, 2);
                if (t4 == 0) {
                    const size_t base = ((size_t)(g * 4 + wid) * BB + b) * TP;
                    int t = tsub0 + q * 16 + g4;
                    if (t < TP)     g_part[base + t] = vlo;
                    if (t + 8 < TP) g_part[base + t + 8] = vhi;
                }
            }
        } else if (have_next) {
            const int nxt = cur ^ 1;
#pragma unroll
            for (int i = 0; i < 13; i++) {
                int e = (tid - 128) + i * 256;
                if (e < XE) {
                    int row = e / GC, col = e - row * GC;
                    unsigned u; CVT_TF32(u, xv[i]);
                    xs[nxt][stage_idx(row, col)] = u;
                }
            }
        }
        __syncthreads();
    }
}

// ---------------------------------------------------------------------------
// SCATTER + tail-zero + pred-sum, one kernel (R14-validated bodies).
// ---------------------------------------------------------------------------
__global__ void scatter_kernel(const float* __restrict__ ph,
                               const float* __restrict__ sil,
                               const float* __restrict__ b2,
                               float* __restrict__ out,
                               float* __restrict__ dpred,
                               int t_out) {
    const int w = (blockIdx.x * blockDim.x + threadIdx.x) >> 5;
    const int lane = threadIdx.x & 31;

    if (w < SW_SCAT) {
        const int b = w / TP;
        const int j = w - b * TP;

        const int hi = g_cum[b * TP + j];
        const int lo = j ? g_cum[b * TP + j - 1] : 0;
        const int d = hi - lo;
        if (d <= 0) return;

        const float4* src = (j < TT_IN)
            ? (const float4*)(ph + ((size_t)b * TT_IN + j) * EMB)
            : (const float4*)sil;
        float4 r0 = __ldcs(src + lane);
        float4 r1 = __ldcs(src + 32 + lane);
        float4 r2 = __ldcs(src + 64 + lane);

        float4* dst = (float4*)(out + ((size_t)b * t_out + lo) * EMB);
        for (int f = 0; f < d; f++, dst += EMB / 4) {
            __stcs(dst + lane,      r0);
            __stcs(dst + 32 + lane, r1);
            __stcs(dst + 64 + lane, r2);
        }
    } else if (w < SW_TOT) {
        const int zw = w - SW_SCAT;
        const int b  = zw / ZWARPS;
        const int zi = zw - b * ZWARPS;
        const int tot = g_cum[b * TP + TP - 1];
        const float4 z = make_float4(0.f, 0.f, 0.f, 0.f);
        for (int t = tot + zi; t < t_out; t += ZWARPS) {
            float4* dst = (float4*)(out + ((size_t)b * t_out + t) * EMB);
            __stcs(dst + lane,      z);
            __stcs(dst + 32 + lane, z);
            __stcs(dst + 64 + lane, z);
        }
    } else {
        const int pw = w - SW_TOT;
        if (pw >= PWARPS) return;
        const int i = pw * 32 + lane;
        if (i >= BB * TP) return;
        float s = b2[0];
#pragma unroll
        for (int q = 0; q < NPART; q++) s += g_part[(size_t)q * BB * TP + i];
        dpred[i] = s;
    }
}

// ---------------------------------------------------------------------------
// Launch
// ---------------------------------------------------------------------------
extern "C" void kernel_launch(void* const* d_in, const int* in_sizes, int n_in,
                              void* d_out, int out_size) {
    const float* ph  = (const float*)d_in[0];   // [32,1024,384]
    const float* sil = (const float*)d_in[1];   // [384]
    const float* w1  = (const float*)d_in[2];   // [384,96,3]
    const float* b1  = (const float*)d_in[3];   // [384]
    const float* w2  = (const float*)d_in[4];   // [1,384,1]
    const float* b2  = (const float*)d_in[5];   // [1]
    const int*   dur = (const int*)d_in[6];     // [32,1025]

    const int t_out = (out_size - BB * TP) / (BB * EMB);

    float* out_exp  = (float*)d_out;                             // [B,t_out,EMB]
    float* out_pred = (float*)d_out + (size_t)BB * t_out * EMB;  // [B,TP]

    const int wblocks = (4 * NWARPS * NKS * 32 + 255) / 256;
    prep_kernel<<<BB + wblocks, 256>>>(dur, w1);

    cudaFuncSetAttribute(conv_mma_kernel,
                         cudaFuncAttributeMaxDynamicSharedMemorySize, SMEM_BYTES);
    conv_mma_kernel<<<CBLOCKS, 384, SMEM_BYTES>>>(ph, sil, b1, w2);

    const int warps = SW_TOT + PWARPS;
    scatter_kernel<<<(warps * 32 + 255) / 256, 256>>>(ph, sil, b2,
                                                      out_exp, out_pred, t_out);
}